// round 16
// baseline (speedup 1.0000x reference)
#include <cuda_runtime.h>
#include <cuda_bf16.h>
#include <cstdint>

#define D 784
#define H 1024
#define BATCH 1024
#define THREADS 512
#define R 7                      // batch rows per CTA
#define NCTAS 147                // 147*7 = 1029 >= 1024
#define CHUNK 56                 // 784 = 14 * 56 (even trip count, unroll-2 friendly)
#define NCHUNKS (D / CHUNK)
#define DPAD (D + 2)                         // padding rows for clamp-free prefetch
#define SX_BYTES (DPAD * 8 * 8)              // sxd[DPAD][8] float2 (duplicated) = 50304
#define SP_BYTES (CHUNK * 16 * 32 * 4)       // sp[CHUNK][16][32] = 114688
#define SMEM_BYTES (SX_BYTES + SP_BYTES)     // 164992

// Scratch (no allocations allowed). +2 rows padding so the prefetch of step
// i+1 at i = D-1 stays in bounds without a clamp.
// g_VW[i*512 + t] = (V[i,2t], V[i,2t+1], W[2t,i], W[2t+1,i])
__device__ float4 g_VW[DPAD * (H / 2)];
__device__ float  g_bias[D];          // bias[i] = b[i] + 0.5 * sum_h V[i,h]

// Two tanh evaluations in ONE MUFU op, input taken from a packed f32x2
// accumulator (halves referenced via mov.b64 -> copy-propagated by ptxas).
__device__ __forceinline__ void tanh2p(unsigned long long a2, float& ta, float& tb) {
    uint32_t pk, tk;
    asm("{\n\t.reg .b32 lo, hi;\n\t"
        "mov.b64 {lo, hi}, %1;\n\t"
        "cvt.rn.f16x2.f32 %0, hi, lo;\n\t}"   // lo half = A.x, hi half = A.y
        : "=r"(pk) : "l"(a2));
    asm("tanh.approx.f16x2 %0, %1;" : "=r"(tk) : "r"(pk));
    asm("{\n\t.reg .b16 l, h;\n\t"
        "mov.b32 {l, h}, %2;\n\t"
        "cvt.f32.f16 %0, l;\n\t"
        "cvt.f32.f16 %1, h;\n\t}"
        : "=f"(ta), "=f"(tb) : "r"(tk));
}

// Packed f32x2 FMA: d.lo = a.lo*b.lo + c.lo ; d.hi = a.hi*b.hi + c.hi
#define FMA_F32X2(d, a, b, c) \
    asm("fma.rn.f32x2 %0, %1, %2, %3;" : "=l"(d) : "l"(a), "l"(b), "l"(c))

// ---------------------------------------------------------------------------
// Fused prep: blockIdx.y < 32 -> build interleaved g_VW tile (transpose W via
//                                smem tile, merge with V)
//             blockIdx.y == 32 -> bias + zero-fill g_VW padding rows
// ---------------------------------------------------------------------------
__global__ void prep_kernel(const float* __restrict__ W,
                            const float* __restrict__ V,
                            const float* __restrict__ bvec) {
    if (blockIdx.y < 32) {
        __shared__ float tile[32][33];
        const int i0 = blockIdx.x * 32;
        const int h0 = blockIdx.y * 32;
        const int tx = threadIdx.x, ty = threadIdx.y;
        #pragma unroll
        for (int j = 0; j < 32; j += 8) {
            int ii = i0 + tx;
            if (ii < D) tile[ty + j][tx] = W[(h0 + ty + j) * D + ii];
        }
        __syncthreads();
        #pragma unroll
        for (int j = 0; j < 32; j += 8) {
            int i = i0 + ty + j;
            if (i < D && tx < 16) {
                int tcol = h0 / 2 + tx;
                float2 v2 = reinterpret_cast<const float2*>(V)[i * (H / 2) + tcol];
                g_VW[i * (H / 2) + tcol] =
                    make_float4(v2.x, v2.y, tile[2 * tx][i - i0], tile[2 * tx + 1][i - i0]);
            }
        }
    } else {
        int lane = threadIdx.x;
        int w    = threadIdx.y;
        #pragma unroll
        for (int k = 0; k < 4; k++) {
            int i = blockIdx.x * 32 + w * 4 + k;
            if (i >= D) continue;
            float s = 0.0f;
            #pragma unroll
            for (int j = 0; j < H / 32; j++) s += V[i * H + j * 32 + lane];
            #pragma unroll
            for (int o = 16; o > 0; o >>= 1)
                s += __shfl_xor_sync(0xffffffffu, s, o);
            if (lane == 0) g_bias[i] = bvec[i] + 0.5f * s;
        }
        // Zero the two padding rows of g_VW (read by the tail prefetch).
        if (blockIdx.x == 0) {
            int t = threadIdx.y * 32 + threadIdx.x;
            for (int k = t; k < 2 * (H / 2); k += 256)
                g_VW[D * (H / 2) + k] = make_float4(0.f, 0.f, 0.f, 0.f);
        }
    }
}

// ---------------------------------------------------------------------------
// Main: one CTA per 7 batch rows; 512 threads (16 warps), 2 h per lane.
// r15 structure (distance-1 clamp-free vw prefetch, unroll 2, 4-lane-cut
// butterfly, deferred epilogue) with packed-f32x2 accumulators:
//   - A[r] is a 64-bit f32x2; 7 FFMA2 replace 14 FFMA per step.
//   - pixel values stored DUPLICATED (x,x) so FFMA2's b-operand loads
//     straight from smem; W pair packed once per step.
// ---------------------------------------------------------------------------
__global__ void __launch_bounds__(THREADS, 1)
nade_main(const float* __restrict__ pixels,
          const float* __restrict__ c,
          float* __restrict__ out) {
    extern __shared__ char smem_raw[];
    float2* sxd = reinterpret_cast<float2*>(smem_raw);            // [DPAD][8] dup pairs
    float*  sp  = reinterpret_cast<float*>(smem_raw + SX_BYTES);  // [CHUNK][16][32]

    const int b0   = blockIdx.x * R;
    const int t    = threadIdx.x;
    const int lane = t & 31;
    const int wid  = t >> 5;

    for (int i = t; i < D; i += THREADS) {
        #pragma unroll
        for (int r = 0; r < R; r++) {
            int br = min(b0 + r, BATCH - 1);
            float x = 0.5f * pixels[br * D + i];
            sxd[i * 8 + r] = make_float2(x, x);
        }
        sxd[i * 8 + 7] = make_float2(0.f, 0.f);
    }
    // Zero the padding rows (keep tail prefetch values benign).
    for (int k = t; k < 2 * 8; k += THREADS) sxd[D * 8 + k] = make_float2(0.f, 0.f);

    unsigned long long A[R];
    {
        float2 cc = reinterpret_cast<const float2*>(c)[t];
        cc.x *= 0.5f; cc.y *= 0.5f;
        unsigned long long a0;
        asm("mov.b64 %0, {%1, %2};" : "=l"(a0) : "f"(cc.x), "f"(cc.y));
        #pragma unroll
        for (int r = 0; r < R; r++) A[r] = a0;
    }
    __syncthreads();

    const bool lo16 = (lane & 16) == 0;
    const bool lo8  = (lane & 8)  == 0;
    const bool lo4  = (lane & 4)  == 0;
    // Slot held by this lane after the 3 fold levels.
    const int rowmap = ((lane >> 4) & 1) | (((lane >> 3) & 1) << 1)
                     | (((lane >> 2) & 1) << 2);
    // STS target: permutation of 32 consecutive floats -> conflict-free.
    const int sts_off = rowmap * 4 + (lane & 3);

    const float4* __restrict__ VW4 = g_VW;

    // Prime the pipeline with step 0's vw (the L2-latency load).
    float4 vw = VW4[t];

    for (int ch = 0; ch < NCHUNKS; ch++) {
        const int ibase = ch * CHUNK;

        #pragma unroll 2
        for (int il = 0; il < CHUNK; il++) {
            const int i = ibase + il;
            // ---- prefetch next step's vw (clamp-free, padded) ----
            float4 vw_n = VW4[(i + 1) * (H / 2) + t];

            // Duplicated pixel pairs for this step (LDS, short latency).
            const unsigned long long* xp =
                reinterpret_cast<const unsigned long long*>(&sxd[i * 8]);
            const ulonglong2* xq = reinterpret_cast<const ulonglong2*>(xp);
            ulonglong2 xab = xq[0];   // rows 0,1
            ulonglong2 xcd = xq[1];   // rows 2,3
            ulonglong2 xef = xq[2];   // rows 4,5
            unsigned long long xg = xp[6];  // row 6

            // ---- compute current step ----
            float p0, p1, p2, p3, p4, p5, p6;
            {
                float t0, t1;
                tanh2p(A[0], t0, t1); p0 = fmaf(vw.y, t1, vw.x * t0);
                tanh2p(A[1], t0, t1); p1 = fmaf(vw.y, t1, vw.x * t0);
                tanh2p(A[2], t0, t1); p2 = fmaf(vw.y, t1, vw.x * t0);
                tanh2p(A[3], t0, t1); p3 = fmaf(vw.y, t1, vw.x * t0);
                tanh2p(A[4], t0, t1); p4 = fmaf(vw.y, t1, vw.x * t0);
                tanh2p(A[5], t0, t1); p5 = fmaf(vw.y, t1, vw.x * t0);
                tanh2p(A[6], t0, t1); p6 = fmaf(vw.y, t1, vw.x * t0);
            }

            // Packed accumulator updates: 7 FFMA2 (f32x2 lanes = exact f32 FMA).
            unsigned long long w2;
            asm("mov.b64 %0, {%1, %2};" : "=l"(w2) : "f"(vw.z), "f"(vw.w));
            FMA_F32X2(A[0], w2, xab.x, A[0]);
            FMA_F32X2(A[1], w2, xab.y, A[1]);
            FMA_F32X2(A[2], w2, xcd.x, A[2]);
            FMA_F32X2(A[3], w2, xcd.y, A[3]);
            FMA_F32X2(A[4], w2, xef.x, A[4]);
            FMA_F32X2(A[5], w2, xef.y, A[5]);
            FMA_F32X2(A[6], w2, xg,    A[6]);

            // Butterfly (r6 shape: shuffles before selects), cut after the
            // mask-4 level; remaining x4 compression in the epilogue.
            float e, f;
            e = __shfl_xor_sync(0xffffffffu, p0, 16);
            f = __shfl_xor_sync(0xffffffffu, p1, 16);
            float q01 = lo16 ? (p0 + e) : (p1 + f);
            e = __shfl_xor_sync(0xffffffffu, p2, 16);
            f = __shfl_xor_sync(0xffffffffu, p3, 16);
            float q23 = lo16 ? (p2 + e) : (p3 + f);
            e = __shfl_xor_sync(0xffffffffu, p4, 16);
            f = __shfl_xor_sync(0xffffffffu, p5, 16);
            float q45 = lo16 ? (p4 + e) : (p5 + f);
            e = __shfl_xor_sync(0xffffffffu, p6, 16);
            float q67 = lo16 ? (p6 + e) : 0.0f;   // slot 7 is zero

            e = __shfl_xor_sync(0xffffffffu, q01, 8);
            f = __shfl_xor_sync(0xffffffffu, q23, 8);
            float q0123 = lo8 ? (q01 + e) : (q23 + f);
            e = __shfl_xor_sync(0xffffffffu, q45, 8);
            f = __shfl_xor_sync(0xffffffffu, q67, 8);
            float q4567 = lo8 ? (q45 + e) : (q67 + f);

            e = __shfl_xor_sync(0xffffffffu, q0123, 4);
            f = __shfl_xor_sync(0xffffffffu, q4567, 4);
            float qq = lo4 ? (q0123 + e) : (q4567 + f);

            // All 32 lanes store: one conflict-free 128B wavefront.
            sp[(il * 16 + wid) * 32 + sts_off] = qq;

            // ---- rotate pipeline ----
            vw = vw_n;
        }

        __syncthreads();

        // Epilogue: for each (step, row) sum 16 warps x 4 lane-partials.
        for (int o = t; o < CHUNK * R; o += THREADS) {
            int il = o / R, r = o % R;
            float s = 0.0f;
            #pragma unroll
            for (int wi = 0; wi < 16; wi++) {
                const float4 q = *reinterpret_cast<const float4*>(
                    &sp[(il * 16 + wi) * 32 + r * 4]);
                s += (q.x + q.y) + (q.z + q.w);
            }
            int i = ibase + il;
            int b = b0 + r;
            if (b < BATCH) out[b * D + i] = fmaf(0.5f, s, g_bias[i]);
        }

        __syncthreads();
    }
}

// ---------------------------------------------------------------------------
extern "C" void kernel_launch(void* const* d_in, const int* in_sizes, int n_in,
                              void* d_out, int out_size) {
    const float* pixels = (const float*)d_in[0];   // [1024, 784]
    const float* W      = (const float*)d_in[1];   // [1024, 784]
    const float* c      = (const float*)d_in[2];   // [1024]
    const float* V      = (const float*)d_in[3];   // [784, 1024]
    const float* bvec   = (const float*)d_in[4];   // [784]
    float* out          = (float*)d_out;           // [1024, 784]

    cudaFuncSetAttribute(nade_main, cudaFuncAttributeMaxDynamicSharedMemorySize,
                         SMEM_BYTES);
    cudaFuncSetAttribute(nade_main, cudaFuncAttributePreferredSharedMemoryCarveout,
                         100);

    prep_kernel<<<dim3(25, 33), dim3(32, 8)>>>(W, V, bvec);
    nade_main<<<NCTAS, THREADS, SMEM_BYTES>>>(pixels, c, out);
}